// round 15
// baseline (speedup 1.0000x reference)
#include <cuda_runtime.h>
#include <cuda_fp16.h>
#include <cstdint>

#define B_ 4
#define N_ 16384
#define M_ 16384
#define K_ 16
#define C_ 64
#define O_ 64
#define G_ 8

typedef unsigned long long ull;

// ---------------- device scratch (no allocations allowed) -------------------
__device__ __align__(16) float  g_WkP[C_ * G_];
__device__ __align__(16) float  g_bkP[G_];
__device__ __align__(16) float  g_WqP[C_ * G_];
__device__ __align__(16) float  g_cw2P[O_ * G_];
__device__ __align__(16) float  g_qconst[G_];
__device__ __align__(16) __half g_xvh[(size_t)B_ * N_ * O_];   // x_v per point (fp16)
__device__ __align__(16) __half g_kgph[(size_t)B_ * N_ * G_];  // x_k@we_w1'(+bias) fp16 (16B row)
__device__ __align__(16) float  g_qw[(size_t)B_ * M_ * G_];    // (cpr-x_q)@we_w1' + we_b
__device__ __align__(16) float4 g_pos4[(size_t)B_ * N_];       // padded pos for 1-LDG gather

// ---------------- f32x2 packed helpers (sm_103a) -----------------------------
__device__ __forceinline__ ull pk2(float lo, float hi) {
    ull r; asm("mov.b64 %0, {%1, %2};" : "=l"(r) : "f"(lo), "f"(hi)); return r;
}
__device__ __forceinline__ float2 upk2(ull v) {
    float2 f; asm("mov.b64 {%0, %1}, %2;" : "=f"(f.x), "=f"(f.y) : "l"(v)); return f;
}
__device__ __forceinline__ void fma2(ull& d, ull a, ull b) {
    asm("fma.rn.f32x2 %0, %1, %2, %0;" : "+l"(d) : "l"(a), "l"(b));
}

// ============================================================================
// k0: fold we_w1*we_s through Wk, Wq, cpe_w2; fold biases.  1 block, 512 thr.
// ============================================================================
__global__ void __launch_bounds__(512) k0_fold(
    const float* __restrict__ Wq, const float* __restrict__ bq,
    const float* __restrict__ Wk, const float* __restrict__ bk,
    const float* __restrict__ cpe_w2, const float* __restrict__ cpe_b2,
    const float* __restrict__ we_w1, const float* __restrict__ we_s,
    const float* __restrict__ we_b)
{
    __shared__ float w1p[512];
    int t = threadIdx.x;
    w1p[t] = we_w1[t] * we_s[t & 7];
    __syncthreads();

    int c = t >> 3, g = t & 7;
    const float4* wk4 = (const float4*)(Wk + c * 64);
    const float4* wq4 = (const float4*)(Wq + c * 64);
    const float4* cw4 = (const float4*)(cpe_w2 + c * 64);
    float aK = 0.f, aQ = 0.f, aC = 0.f;
    #pragma unroll
    for (int o4 = 0; o4 < 16; o4++) {
        float4 k4 = wk4[o4];
        float4 q4 = wq4[o4];
        float4 c4 = cw4[o4];
        float w0 = w1p[(4 * o4 + 0) * 8 + g];
        float w1 = w1p[(4 * o4 + 1) * 8 + g];
        float w2 = w1p[(4 * o4 + 2) * 8 + g];
        float w3 = w1p[(4 * o4 + 3) * 8 + g];
        aK = fmaf(k4.x, w0, aK); aK = fmaf(k4.y, w1, aK);
        aK = fmaf(k4.z, w2, aK); aK = fmaf(k4.w, w3, aK);
        aQ = fmaf(q4.x, w0, aQ); aQ = fmaf(q4.y, w1, aQ);
        aQ = fmaf(q4.z, w2, aQ); aQ = fmaf(q4.w, w3, aQ);
        aC = fmaf(c4.x, w0, aC); aC = fmaf(c4.y, w1, aC);
        aC = fmaf(c4.z, w2, aC); aC = fmaf(c4.w, w3, aC);
    }
    g_WkP[t]  = aK;
    g_WqP[t]  = aQ;
    g_cw2P[t] = aC;

    if (t < 8) {
        float bkp = 0.f, qc = we_b[t];
        #pragma unroll 8
        for (int o = 0; o < 64; o++) {
            float wp = w1p[o * 8 + t];
            bkp = fmaf(bk[o], wp, bkp);
            qc  = fmaf(cpe_b2[o] - bq[o], wp, qc);
        }
        g_bkP[t]    = bkp;
        g_qconst[t] = qc;
    }
}

// ============================================================================
// k12: fused point-side (z=0) and center-side (z=1) projections; f32x2 packed
// inner loops; vectorized (float4) feature staging.  grid (256, B, 2).
// ============================================================================
__global__ void __launch_bounds__(256) k12(
    const float* __restrict__ fea, const float* __restrict__ Wv, const float* __restrict__ bv,
    const float* __restrict__ pos,
    const float* __restrict__ cfea, const float* __restrict__ cpos,
    const float* __restrict__ cpe_w1, const float* __restrict__ cpe_s, const float* __restrict__ cpe_b)
{
    __shared__ __align__(16) float smem[8784];
    int t = threadIdx.x;
    int b = blockIdx.y;

    if (blockIdx.z == 0) {
        float* sfea = smem;              // [64][64]
        float* sWv  = smem + 4096;       // [64][64]
        float* sWkP = smem + 8192;       // [64][8]
        float* sbkP = smem + 8704;       // [8]

        int n0 = blockIdx.x * 64;
        const float* fbase = fea + (size_t)b * C_ * N_ + n0;
        for (int i = t; i < 1024; i += 256) {
            int c = i >> 4, n4 = i & 15;
            ((float4*)&sfea[c * 64])[n4] =
                ((const float4*)(fbase + (size_t)c * N_))[n4];
        }
        for (int i = t; i < 1024; i += 256)
            ((float4*)sWv)[i] = ((const float4*)Wv)[i];
        for (int i = t; i < 512;  i += 256) sWkP[i] = g_WkP[i];
        if (t < 8) sbkP[t] = g_bkP[t];
        if (t < 64) {
            const float* pp = pos + ((size_t)b * N_ + n0 + t) * 3;
            g_pos4[(size_t)b * N_ + n0 + t] = make_float4(pp[0], pp[1], pp[2], 0.f);
        }
        __syncthreads();

        int n = t & 63, q = t >> 6;
        int ob = q * 16;
        int g0 = 2 * q;
        ull accp[8];
        #pragma unroll
        for (int u = 0; u < 8; u++) accp[u] = *(const ull*)&bv[ob + 2 * u];
        ull akp = *(const ull*)&sbkP[g0];

        #pragma unroll 4
        for (int c = 0; c < 64; c++) {
            float f = sfea[c * 64 + n];
            ull fp = pk2(f, f);
            const ulonglong2* wv2 = (const ulonglong2*)&sWv[c * 64 + ob];
            ulonglong2 wv0 = wv2[0], wv1 = wv2[1], wv2b = wv2[2], wv3 = wv2[3];
            fma2(accp[0], fp, wv0.x); fma2(accp[1], fp, wv0.y);
            fma2(accp[2], fp, wv1.x); fma2(accp[3], fp, wv1.y);
            fma2(accp[4], fp, wv2b.x); fma2(accp[5], fp, wv2b.y);
            fma2(accp[6], fp, wv3.x); fma2(accp[7], fp, wv3.y);
            fma2(akp, fp, *(const ull*)&sWkP[c * 8 + g0]);
        }

        __half* xvo = &g_xvh[((size_t)b * N_ + n0 + n) * O_ + ob];
        union { uint4 u; __half2 h[4]; } p0, p1;
        #pragma unroll
        for (int u = 0; u < 4; u++) {
            float2 a = upk2(accp[u]);
            p0.h[u] = __floats2half2_rn(a.x, a.y);
        }
        #pragma unroll
        for (int u = 0; u < 4; u++) {
            float2 a = upk2(accp[4 + u]);
            p1.h[u] = __floats2half2_rn(a.x, a.y);
        }
        *(uint4*)xvo       = p0.u;
        *(uint4*)(xvo + 8) = p1.u;
        float2 ak = upk2(akp);
        *(__half2*)&g_kgph[((size_t)b * N_ + n0 + n) * G_ + g0] = __floats2half2_rn(ak.x, ak.y);
    } else {
        float* sfea  = smem;             // [64][64]
        float* sWqP  = smem + 4096;      // [64][8]
        float* scw2P = smem + 4608;      // [64][8]
        float* sw1   = smem + 5120;      // [3][64]
        float* ss    = smem + 5312;      // [64]
        float* sb    = smem + 5376;      // [64]
        float* sqc   = smem + 5440;      // [8]

        int m0 = blockIdx.x * 64;
        const float* fbase = cfea + (size_t)b * C_ * M_ + m0;
        for (int i = t; i < 1024; i += 256) {
            int c = i >> 4, m4 = i & 15;
            ((float4*)&sfea[c * 64])[m4] =
                ((const float4*)(fbase + (size_t)c * M_))[m4];
        }
        for (int i = t; i < 512; i += 256) { sWqP[i] = g_WqP[i]; scw2P[i] = g_cw2P[i]; }
        if (t < 192) sw1[t] = cpe_w1[t];
        if (t < 64)  { ss[t] = cpe_s[t]; sb[t] = cpe_b[t]; }
        if (t < 8)   sqc[t] = g_qconst[t];
        __syncthreads();

        int m = t & 63, q = t >> 6, g0 = 2 * q;
        ull ap = *(const ull*)&sqc[g0];

        #pragma unroll 4
        for (int c = 0; c < 64; c++) {
            float f = sfea[c * 64 + m];
            ull fp = pk2(-f, -f);
            fma2(ap, fp, *(const ull*)&sWqP[c * 8 + g0]);
        }
        const float* cp = cpos + ((size_t)b * M_ + m0 + m) * 3;
        float x = cp[0], y = cp[1], z = cp[2];
        #pragma unroll 4
        for (int o = 0; o < 64; o++) {
            float d  = fmaf(z, sw1[128 + o], fmaf(y, sw1[64 + o], x * sw1[o]));
            float rc = fmaxf(fmaf(d, ss[o], sb[o]), 0.f);
            ull rcp = pk2(rc, rc);
            fma2(ap, rcp, *(const ull*)&scw2P[o * 8 + g0]);
        }
        float2 a = upk2(ap);
        *(float2*)&g_qw[((size_t)b * M_ + m0 + m) * G_ + g0] = make_float2(a.x, a.y);
    }
}

// ============================================================================
// k3: main attention. 2 centers/warp, 16 centers/block, 4 blocks/SM.
// Phase C: W2 kept fp32 in smem, consumed as ulonglong2 -> fma.rn.f32x2
// with ZERO conversions (removes ~320 F2F per lane).
// ============================================================================
__global__ void __launch_bounds__(256, 4) k3_main(
    const float* __restrict__ cpos,
    const int*   __restrict__ idx,
    const float* __restrict__ pe_w1, const float* __restrict__ pe_s, const float* __restrict__ pe_b,
    const float* __restrict__ pe_w2, const float* __restrict__ pe_b2,
    const float* __restrict__ we_w2, const float* __restrict__ we_b2,
    float* __restrict__ out)
{
    __shared__ __align__(16) float  s_pew2f[64 * 68];        // [j][o] fp32, pad 68
    __shared__ __align__(16) __half s_stgh[8 * 2 * 8 * 36];  // [w][c][g][36] fp16
    __shared__ __align__(16) float  s_wf[16 * 16 * 8];       // softmax weights fp32
    __shared__ __align__(16) float4 s_npos[16 * 16];
    __shared__ __align__(16) float  s_out[16 * 68];
    __shared__ int   s_nidx[16 * 16];
    __shared__ float s_pes[64], s_peb[64], s_peb2[64];
    __shared__ __align__(16) float s_wew2[64];
    __shared__ __align__(16) float s_web2[8];

    int b = blockIdx.y;
    int m_base = blockIdx.x * 16;
    int t = threadIdx.x;
    int w = t >> 5, l = t & 31;

    // ---- cooperative constant loads (float4: 68-float rows are 16B-aligned) ----
    for (int i = t; i < 1024; i += 256) {
        int j = i >> 4, o4 = i & 15;
        ((float4*)&s_pew2f[j * 68])[o4] = ((const float4*)pe_w2)[j * 16 + o4];
    }
    for (int i = t; i < 64; i += 256) { s_pes[i] = pe_s[i]; s_peb[i] = pe_b[i]; s_peb2[i] = pe_b2[i]; }
    if (t < 64) s_wew2[t] = we_w2[t];
    if (t < 8)  s_web2[t] = we_b2[t];

    int half_ = l >> 4;           // 0/1: which center of the warp's pair
    int cc    = w * 2 + half_;
    int m     = m_base + cc;

    // ---- neighbor setup: lane (half_, k=l&15); one LDG.128 per gather ----
    {
        int k = l & 15;
        int n = idx[((size_t)b * M_ + m) * K_ + k];
        s_nidx[cc * 16 + k] = n;
        float4 pq = g_pos4[(size_t)b * N_ + n];
        const float* cp = cpos + ((size_t)b * M_ + m) * 3;
        s_npos[cc * 16 + k] = make_float4(pq.x - cp[0], pq.y - cp[1], pq.z - cp[2], 0.f);
    }
    __syncthreads();

    // ---- Phase A: logits + softmax (f32x2 logit loop, fp16 kgp 1-LDG row) ----
    {
        int k = l & 15;
        int n = s_nidx[cc * 16 + k];
        const float4* qwp = (const float4*)&g_qw[((size_t)b * M_ + m) * G_];
        float4 qa = qwp[0], qb = qwp[1];
        uint4 kg = *(const uint4*)&g_kgph[((size_t)b * N_ + n) * G_];
        float2 k01 = __half22float2(*reinterpret_cast<__half2*>(&kg.x));
        float2 k23 = __half22float2(*reinterpret_cast<__half2*>(&kg.y));
        float2 k45 = __half22float2(*reinterpret_cast<__half2*>(&kg.z));
        float2 k67 = __half22float2(*reinterpret_cast<__half2*>(&kg.w));
        float h[8];
        h[0] = fmaxf(k01.x + qa.x, 0.f); h[1] = fmaxf(k01.y + qa.y, 0.f);
        h[2] = fmaxf(k23.x + qa.z, 0.f); h[3] = fmaxf(k23.y + qa.w, 0.f);
        h[4] = fmaxf(k45.x + qb.x, 0.f); h[5] = fmaxf(k45.y + qb.y, 0.f);
        h[6] = fmaxf(k67.x + qb.z, 0.f); h[7] = fmaxf(k67.y + qb.w, 0.f);

        ull lgp[4];
        #pragma unroll
        for (int p = 0; p < 4; p++) lgp[p] = *(const ull*)&s_web2[2 * p];
        #pragma unroll
        for (int j = 0; j < 8; j++) {
            ull hp = pk2(h[j], h[j]);
            const ulonglong2* wr = (const ulonglong2*)&s_wew2[j * 8];
            ulonglong2 wa = wr[0], wb = wr[1];
            fma2(lgp[0], hp, wa.x); fma2(lgp[1], hp, wa.y);
            fma2(lgp[2], hp, wb.x); fma2(lgp[3], hp, wb.y);
        }
        float lg[8];
        #pragma unroll
        for (int p = 0; p < 4; p++) {
            float2 v = upk2(lgp[p]);
            lg[2 * p] = v.x; lg[2 * p + 1] = v.y;
        }
        float mx[8];
        #pragma unroll
        for (int u = 0; u < 8; u++) mx[u] = lg[u];
        #pragma unroll
        for (int mask = 1; mask <= 8; mask <<= 1)
            #pragma unroll
            for (int u = 0; u < 8; u++)
                mx[u] = fmaxf(mx[u], __shfl_xor_sync(0xffffffffu, mx[u], mask));
        float e[8], sm[8];
        #pragma unroll
        for (int u = 0; u < 8; u++) { e[u] = __expf(lg[u] - mx[u]); sm[u] = e[u]; }
        #pragma unroll
        for (int mask = 1; mask <= 8; mask <<= 1)
            #pragma unroll
            for (int u = 0; u < 8; u++)
                sm[u] += __shfl_xor_sync(0xffffffffu, sm[u], mask);
        float* wp = &s_wf[(cc * 16 + k) * 8];
        *(float4*)&wp[0] = make_float4(e[0] / sm[0], e[1] / sm[1], e[2] / sm[2], e[3] / sm[3]);
        *(float4*)&wp[4] = make_float4(e[4] / sm[4], e[5] / sm[5], e[6] / sm[6], e[7] / sm[7]);
    }
    __syncwarp();

    // ---- Phase B: packed f32x2. Sp0[c][p] = (S[2p][j0], S[2p+1][j0]); Sp1: j1 ----
    ull S0p[2][4], S1p[2][4];
    {
        int j0 = 2 * l, j1 = j0 + 1;
        float wx0 = pe_w1[j0], wy0 = pe_w1[64 + j0], wz0 = pe_w1[128 + j0];
        float wx1 = pe_w1[j1], wy1 = pe_w1[64 + j1], wz1 = pe_w1[128 + j1];
        float ps0 = s_pes[j0], pb0 = s_peb[j0];
        float ps1 = s_pes[j1], pb1 = s_peb[j1];

        #pragma unroll
        for (int c = 0; c < 2; c++) {
            int ccB = w * 2 + c;
            #pragma unroll
            for (int p = 0; p < 4; p++) { S0p[c][p] = 0ull; S1p[c][p] = 0ull; }
            #pragma unroll
            for (int kk = 0; kk < 16; kk++) {
                float4 np = s_npos[ccB * 16 + kk];
                float d0 = fmaf(np.z, wz0, fmaf(np.y, wy0, np.x * wx0));
                float d1 = fmaf(np.z, wz1, fmaf(np.y, wy1, np.x * wx1));
                float t0 = fmaxf(fmaf(d0, ps0, pb0), 0.f);
                float t1 = fmaxf(fmaf(d1, ps1, pb1), 0.f);
                ull t0p = pk2(t0, t0);
                ull t1p = pk2(t1, t1);
                const float* wrow = &s_wf[(ccB * 16 + kk) * 8];
                ulonglong2 wa = *(const ulonglong2*)wrow;
                ulonglong2 wb = *(const ulonglong2*)(wrow + 4);
                fma2(S0p[c][0], t0p, wa.x); fma2(S1p[c][0], t1p, wa.x);
                fma2(S0p[c][1], t0p, wa.y); fma2(S1p[c][1], t1p, wa.y);
                fma2(S0p[c][2], t0p, wb.x); fma2(S1p[c][2], t1p, wb.x);
                fma2(S0p[c][3], t0p, wb.y); fma2(S1p[c][3], t1p, wb.y);
            }
        }
    }

    // ---- Phase C: chunked over j; W2 fp32 -> pure f32x2, no conversions ----
    {
        int lo = l & 15;
        int o0 = lo * 4;
        int g  = lo >> 1;
        ull acc0 = *(const ull*)&s_peb2[o0];       // (o0, o1)
        ull acc1 = *(const ull*)&s_peb2[o0 + 2];   // (o2, o3)
        __half* warpStg = &s_stgh[w * (2 * 8 * 36)];
        const __half* stg = &warpStg[(half_ * 8 + g) * 36];
        int myChunk = l >> 4;
        int jl = (l & 15) * 2;

        #pragma unroll
        for (int ch = 0; ch < 2; ch++) {
            if (myChunk == ch) {
                #pragma unroll
                for (int c = 0; c < 2; c++) {
                    __half* dst = &warpStg[(c * 8) * 36];
                    #pragma unroll
                    for (int p = 0; p < 4; p++) {
                        float2 a0 = upk2(S0p[c][p]);
                        float2 a1 = upk2(S1p[c][p]);
                        *(__half2*)&dst[(2 * p)     * 36 + jl] = __floats2half2_rn(a0.x, a1.x);
                        *(__half2*)&dst[(2 * p + 1) * 36 + jl] = __floats2half2_rn(a0.y, a1.y);
                    }
                }
            }
            __syncwarp();
            int jb = ch * 32;
            #pragma unroll
            for (int jq = 0; jq < 32; jq += 4) {
                uint2 rs = *(const uint2*)&stg[jq];
                float2 sa = __half22float2(*reinterpret_cast<__half2*>(&rs.x));
                float2 sb = __half22float2(*reinterpret_cast<__half2*>(&rs.y));
                ull s0 = pk2(sa.x, sa.x);
                ull s1 = pk2(sa.y, sa.y);
                ull s2 = pk2(sb.x, sb.x);
                ull s3 = pk2(sb.y, sb.y);
                const float* wr = &s_pew2f[(jb + jq) * 68 + o0];
                ulonglong2 w0 = *(const ulonglong2*)wr;
                ulonglong2 w1 = *(const ulonglong2*)(wr + 68);
                ulonglong2 w2 = *(const ulonglong2*)(wr + 136);
                ulonglong2 w3 = *(const ulonglong2*)(wr + 204);
                fma2(acc0, s0, w0.x); fma2(acc1, s0, w0.y);
                fma2(acc0, s1, w1.x); fma2(acc1, s1, w1.y);
                fma2(acc0, s2, w2.x); fma2(acc1, s2, w2.y);
                fma2(acc0, s3, w3.x); fma2(acc1, s3, w3.y);
            }
            __syncwarp();
        }

        // xv gather part (fp16 rows, 128B per point), packed accumulate
        const __half* xvb = &g_xvh[((size_t)b * N_) * O_];
        #pragma unroll
        for (int kk = 0; kk < 16; kk++) {
            int   n  = s_nidx[cc * 16 + kk];
            float wk = s_wf[(cc * 16 + kk) * 8 + g];
            uint2 xr = *(const uint2*)&xvb[(size_t)n * O_ + o0];
            float2 x01 = __half22float2(*reinterpret_cast<__half2*>(&xr.x));
            float2 x23 = __half22float2(*reinterpret_cast<__half2*>(&xr.y));
            ull wkp = pk2(wk, wk);
            fma2(acc0, wkp, pk2(x01.x, x01.y));
            fma2(acc1, wkp, pk2(x23.x, x23.y));
        }
        float2 r0 = upk2(acc0);
        float2 r1 = upk2(acc1);
        *(float4*)&s_out[cc * 68 + o0] = make_float4(r0.x, r0.y, r1.x, r1.y);
    }
    __syncthreads();

    // ---- coalesced transposed store: out[b][o][m_base + 0..15] ----
    {
        int mm = t & 15;
        #pragma unroll
        for (int o = t >> 4; o < 64; o += 16)
            out[((size_t)b * O_ + o) * M_ + m_base + mm] = s_out[mm * 68 + o];
    }
}

// ============================================================================
extern "C" void kernel_launch(void* const* d_in, const int* in_sizes, int n_in,
                              void* d_out, int out_size)
{
    const float* center_pos = (const float*)d_in[0];
    const float* center_fea = (const float*)d_in[1];
    const float* pos        = (const float*)d_in[2];
    const float* fea        = (const float*)d_in[3];
    const int*   idx        = (const int*)  d_in[4];
    const float* Wq   = (const float*)d_in[5];
    const float* bq   = (const float*)d_in[6];
    const float* Wk   = (const float*)d_in[7];
    const float* bk   = (const float*)d_in[8];
    const float* Wv   = (const float*)d_in[9];
    const float* bv   = (const float*)d_in[10];
    const float* cpe_w1 = (const float*)d_in[11];
    const float* cpe_s  = (const float*)d_in[12];
    const float* cpe_b  = (const float*)d_in[13];
    const float* cpe_w2 = (const float*)d_in[14];
    const float* cpe_b2 = (const float*)d_in[15];
    const float* pe_w1  = (const float*)d_in[16];
    const float* pe_s   = (const float*)d_in[17];
    const float* pe_b   = (const float*)d_in[18];
    const float* pe_w2  = (const float*)d_in[19];
    const float* pe_b2  = (const float*)d_in[20];
    const float* we_w1  = (const float*)d_in[21];
    const float* we_s   = (const float*)d_in[22];
    const float* we_b   = (const float*)d_in[23];
    const float* we_w2  = (const float*)d_in[24];
    const float* we_b2  = (const float*)d_in[25];
    float* out = (float*)d_out;

    k0_fold<<<1, 512>>>(Wq, bq, Wk, bk, cpe_w2, cpe_b2, we_w1, we_s, we_b);

    dim3 g12(N_ / 64, B_, 2);
    k12<<<g12, 256>>>(fea, Wv, bv, pos, center_fea, center_pos,
                      cpe_w1, cpe_s, cpe_b);

    dim3 g3(M_ / 16, B_);
    k3_main<<<g3, 256>>>(center_pos, idx,
                         pe_w1, pe_s, pe_b, pe_w2, pe_b2,
                         we_w2, we_b2, out);
}

// round 16
// speedup vs baseline: 1.1003x; 1.1003x over previous
#include <cuda_runtime.h>
#include <cuda_fp16.h>
#include <cstdint>

#define B_ 4
#define N_ 16384
#define M_ 16384
#define K_ 16
#define C_ 64
#define O_ 64
#define G_ 8

typedef unsigned long long ull;

// ---------------- device scratch (no allocations allowed) -------------------
__device__ __align__(16) float  g_WkP[C_ * G_];
__device__ __align__(16) float  g_bkP[G_];
__device__ __align__(16) float  g_WqP[C_ * G_];
__device__ __align__(16) float  g_cw2P[O_ * G_];
__device__ __align__(16) float  g_qconst[G_];
__device__ __align__(16) __half g_xvh[(size_t)B_ * N_ * O_];   // x_v per point (fp16)
__device__ __align__(16) __half g_kgph[(size_t)B_ * N_ * G_];  // x_k@we_w1'(+bias) fp16 (16B row)
__device__ __align__(16) float  g_qw[(size_t)B_ * M_ * G_];    // (cpr-x_q)@we_w1' + we_b
__device__ __align__(16) float4 g_pos4[(size_t)B_ * N_];       // padded pos for 1-LDG gather

// ---------------- f32x2 packed helpers (sm_103a) -----------------------------
__device__ __forceinline__ ull pk2(float lo, float hi) {
    ull r; asm("mov.b64 %0, {%1, %2};" : "=l"(r) : "f"(lo), "f"(hi)); return r;
}
__device__ __forceinline__ float2 upk2(ull v) {
    float2 f; asm("mov.b64 {%0, %1}, %2;" : "=f"(f.x), "=f"(f.y) : "l"(v)); return f;
}
__device__ __forceinline__ void fma2(ull& d, ull a, ull b) {
    asm("fma.rn.f32x2 %0, %1, %2, %0;" : "+l"(d) : "l"(a), "l"(b));
}

// Load 4 consecutive halfs -> float4 (8-byte aligned)
__device__ __forceinline__ float4 ld_h4(const __half* p) {
    uint2 r = *(const uint2*)p;
    float2 f0 = __half22float2(*reinterpret_cast<__half2*>(&r.x));
    float2 f1 = __half22float2(*reinterpret_cast<__half2*>(&r.y));
    return make_float4(f0.x, f0.y, f1.x, f1.y);
}

__device__ __forceinline__ uint32_t h2u(float a, float b) {
    __half2 h = __floats2half2_rn(a, b);
    return *reinterpret_cast<uint32_t*>(&h);
}

// mma.sync m16n8k16 f16 inputs, f32 accumulate (C = 0)
__device__ __forceinline__ void mma16816(
    float& d0, float& d1, float& d2, float& d3,
    uint32_t a0, uint32_t a1, uint32_t a2, uint32_t a3,
    uint32_t b0, uint32_t b1)
{
    asm volatile(
        "mma.sync.aligned.m16n8k16.row.col.f32.f16.f16.f32 "
        "{%0,%1,%2,%3}, {%4,%5,%6,%7}, {%8,%9}, {%10,%11,%12,%13};"
        : "=f"(d0), "=f"(d1), "=f"(d2), "=f"(d3)
        : "r"(a0), "r"(a1), "r"(a2), "r"(a3), "r"(b0), "r"(b1),
          "f"(0.0f), "f"(0.0f), "f"(0.0f), "f"(0.0f));
}

// ============================================================================
// k0: fold we_w1*we_s through Wk, Wq, cpe_w2; fold biases.  1 block, 512 thr.
// ============================================================================
__global__ void __launch_bounds__(512) k0_fold(
    const float* __restrict__ Wq, const float* __restrict__ bq,
    const float* __restrict__ Wk, const float* __restrict__ bk,
    const float* __restrict__ cpe_w2, const float* __restrict__ cpe_b2,
    const float* __restrict__ we_w1, const float* __restrict__ we_s,
    const float* __restrict__ we_b)
{
    __shared__ float w1p[512];
    int t = threadIdx.x;
    w1p[t] = we_w1[t] * we_s[t & 7];
    __syncthreads();

    int c = t >> 3, g = t & 7;
    const float4* wk4 = (const float4*)(Wk + c * 64);
    const float4* wq4 = (const float4*)(Wq + c * 64);
    const float4* cw4 = (const float4*)(cpe_w2 + c * 64);
    float aK = 0.f, aQ = 0.f, aC = 0.f;
    #pragma unroll
    for (int o4 = 0; o4 < 16; o4++) {
        float4 k4 = wk4[o4];
        float4 q4 = wq4[o4];
        float4 c4 = cw4[o4];
        float w0 = w1p[(4 * o4 + 0) * 8 + g];
        float w1 = w1p[(4 * o4 + 1) * 8 + g];
        float w2 = w1p[(4 * o4 + 2) * 8 + g];
        float w3 = w1p[(4 * o4 + 3) * 8 + g];
        aK = fmaf(k4.x, w0, aK); aK = fmaf(k4.y, w1, aK);
        aK = fmaf(k4.z, w2, aK); aK = fmaf(k4.w, w3, aK);
        aQ = fmaf(q4.x, w0, aQ); aQ = fmaf(q4.y, w1, aQ);
        aQ = fmaf(q4.z, w2, aQ); aQ = fmaf(q4.w, w3, aQ);
        aC = fmaf(c4.x, w0, aC); aC = fmaf(c4.y, w1, aC);
        aC = fmaf(c4.z, w2, aC); aC = fmaf(c4.w, w3, aC);
    }
    g_WkP[t]  = aK;
    g_WqP[t]  = aQ;
    g_cw2P[t] = aC;

    if (t < 8) {
        float bkp = 0.f, qc = we_b[t];
        #pragma unroll 8
        for (int o = 0; o < 64; o++) {
            float wp = w1p[o * 8 + t];
            bkp = fmaf(bk[o], wp, bkp);
            qc  = fmaf(cpe_b2[o] - bq[o], wp, qc);
        }
        g_bkP[t]    = bkp;
        g_qconst[t] = qc;
    }
}

// ============================================================================
// k12: fused point-side (z=0) and center-side (z=1) projections; f32x2 packed
// inner loops; vectorized (float4) feature staging.  grid (256, B, 2).
// ============================================================================
__global__ void __launch_bounds__(256) k12(
    const float* __restrict__ fea, const float* __restrict__ Wv, const float* __restrict__ bv,
    const float* __restrict__ pos,
    const float* __restrict__ cfea, const float* __restrict__ cpos,
    const float* __restrict__ cpe_w1, const float* __restrict__ cpe_s, const float* __restrict__ cpe_b)
{
    __shared__ __align__(16) float smem[8784];
    int t = threadIdx.x;
    int b = blockIdx.y;

    if (blockIdx.z == 0) {
        float* sfea = smem;              // [64][64]
        float* sWv  = smem + 4096;       // [64][64]
        float* sWkP = smem + 8192;       // [64][8]
        float* sbkP = smem + 8704;       // [8]

        int n0 = blockIdx.x * 64;
        const float* fbase = fea + (size_t)b * C_ * N_ + n0;
        for (int i = t; i < 1024; i += 256) {
            int c = i >> 4, n4 = i & 15;
            ((float4*)&sfea[c * 64])[n4] =
                ((const float4*)(fbase + (size_t)c * N_))[n4];
        }
        for (int i = t; i < 1024; i += 256)
            ((float4*)sWv)[i] = ((const float4*)Wv)[i];
        for (int i = t; i < 512;  i += 256) sWkP[i] = g_WkP[i];
        if (t < 8) sbkP[t] = g_bkP[t];
        if (t < 64) {
            const float* pp = pos + ((size_t)b * N_ + n0 + t) * 3;
            g_pos4[(size_t)b * N_ + n0 + t] = make_float4(pp[0], pp[1], pp[2], 0.f);
        }
        __syncthreads();

        int n = t & 63, q = t >> 6;
        int ob = q * 16;
        int g0 = 2 * q;
        ull accp[8];
        #pragma unroll
        for (int u = 0; u < 8; u++) accp[u] = *(const ull*)&bv[ob + 2 * u];
        ull akp = *(const ull*)&sbkP[g0];

        #pragma unroll 4
        for (int c = 0; c < 64; c++) {
            float f = sfea[c * 64 + n];
            ull fp = pk2(f, f);
            const ulonglong2* wv2 = (const ulonglong2*)&sWv[c * 64 + ob];
            ulonglong2 wv0 = wv2[0], wv1 = wv2[1], wv2b = wv2[2], wv3 = wv2[3];
            fma2(accp[0], fp, wv0.x); fma2(accp[1], fp, wv0.y);
            fma2(accp[2], fp, wv1.x); fma2(accp[3], fp, wv1.y);
            fma2(accp[4], fp, wv2b.x); fma2(accp[5], fp, wv2b.y);
            fma2(accp[6], fp, wv3.x); fma2(accp[7], fp, wv3.y);
            fma2(akp, fp, *(const ull*)&sWkP[c * 8 + g0]);
        }

        __half* xvo = &g_xvh[((size_t)b * N_ + n0 + n) * O_ + ob];
        union { uint4 u; __half2 h[4]; } p0, p1;
        #pragma unroll
        for (int u = 0; u < 4; u++) {
            float2 a = upk2(accp[u]);
            p0.h[u] = __floats2half2_rn(a.x, a.y);
        }
        #pragma unroll
        for (int u = 0; u < 4; u++) {
            float2 a = upk2(accp[4 + u]);
            p1.h[u] = __floats2half2_rn(a.x, a.y);
        }
        *(uint4*)xvo       = p0.u;
        *(uint4*)(xvo + 8) = p1.u;
        float2 ak = upk2(akp);
        *(__half2*)&g_kgph[((size_t)b * N_ + n0 + n) * G_ + g0] = __floats2half2_rn(ak.x, ak.y);
    } else {
        float* sfea  = smem;             // [64][64]
        float* sWqP  = smem + 4096;      // [64][8]
        float* scw2P = smem + 4608;      // [64][8]
        float* sw1   = smem + 5120;      // [3][64]
        float* ss    = smem + 5312;      // [64]
        float* sb    = smem + 5376;      // [64]
        float* sqc   = smem + 5440;      // [8]

        int m0 = blockIdx.x * 64;
        const float* fbase = cfea + (size_t)b * C_ * M_ + m0;
        for (int i = t; i < 1024; i += 256) {
            int c = i >> 4, m4 = i & 15;
            ((float4*)&sfea[c * 64])[m4] =
                ((const float4*)(fbase + (size_t)c * M_))[m4];
        }
        for (int i = t; i < 512; i += 256) { sWqP[i] = g_WqP[i]; scw2P[i] = g_cw2P[i]; }
        if (t < 192) sw1[t] = cpe_w1[t];
        if (t < 64)  { ss[t] = cpe_s[t]; sb[t] = cpe_b[t]; }
        if (t < 8)   sqc[t] = g_qconst[t];
        __syncthreads();

        int m = t & 63, q = t >> 6, g0 = 2 * q;
        ull ap = *(const ull*)&sqc[g0];

        #pragma unroll 4
        for (int c = 0; c < 64; c++) {
            float f = sfea[c * 64 + m];
            ull fp = pk2(-f, -f);
            fma2(ap, fp, *(const ull*)&sWqP[c * 8 + g0]);
        }
        const float* cp = cpos + ((size_t)b * M_ + m0 + m) * 3;
        float x = cp[0], y = cp[1], z = cp[2];
        #pragma unroll 4
        for (int o = 0; o < 64; o++) {
            float d  = fmaf(z, sw1[128 + o], fmaf(y, sw1[64 + o], x * sw1[o]));
            float rc = fmaxf(fmaf(d, ss[o], sb[o]), 0.f);
            ull rcp = pk2(rc, rc);
            fma2(ap, rcp, *(const ull*)&scw2P[o * 8 + g0]);
        }
        float2 a = upk2(ap);
        *(float2*)&g_qw[((size_t)b * M_ + m0 + m) * G_ + g0] = make_float2(a.x, a.y);
    }
}

// ============================================================================
// k3: main attention. 2 centers/warp, 16 centers/block, 4 blocks/SM.
// Phase B now uses tensor-core mma.sync (m16n8k16): S = T^T @ W per center,
// D fragments staged directly to the fp16 S buffer (full 64-j rows).
// Phase A (f32x2) and Phase C (fp16 W2, R14 form) unchanged.
// ============================================================================
__global__ void __launch_bounds__(256, 4) k3_main(
    const float* __restrict__ cpos,
    const int*   __restrict__ idx,
    const float* __restrict__ pe_w1, const float* __restrict__ pe_s, const float* __restrict__ pe_b,
    const float* __restrict__ pe_w2, const float* __restrict__ pe_b2,
    const float* __restrict__ we_w2, const float* __restrict__ we_b2,
    float* __restrict__ out)
{
    __shared__ __align__(16) __half s_pew2h[64 * 68];       // [j][o] fp16, pad 68
    __shared__ __align__(16) __half s_stgh[16 * 8 * 68];    // [cc][g][68] fp16 S
    __shared__ __align__(16) float  s_wf[16 * 16 * 8];      // softmax weights fp32
    __shared__ __align__(16) float4 s_npos[16 * 16];
    __shared__ __align__(16) float4 s_w1ps4[64];            // (w1*ps).xyz, pb
    __shared__ __align__(16) float  s_out[16 * 68];
    __shared__ int   s_nidx[16 * 16];
    __shared__ float s_peb2[64];
    __shared__ __align__(16) float s_wew2[64];
    __shared__ __align__(16) float s_web2[8];

    int b = blockIdx.y;
    int m_base = blockIdx.x * 16;
    int t = threadIdx.x;
    int w = t >> 5, l = t & 31;

    // ---- cooperative constant loads ----
    for (int i = t; i < 64 * 64; i += 256) {
        int j = i >> 6, o = i & 63;
        s_pew2h[j * 68 + o] = __float2half_rn(pe_w2[i]);
    }
    for (int i = t; i < 64; i += 256) s_peb2[i] = pe_b2[i];
    if (t < 64) {
        float sc = pe_s[t];
        s_w1ps4[t] = make_float4(pe_w1[t] * sc, pe_w1[64 + t] * sc,
                                 pe_w1[128 + t] * sc, pe_b[t]);
        s_wew2[t] = we_w2[t];
    }
    if (t < 8) s_web2[t] = we_b2[t];

    int half_ = l >> 4;           // 0/1: which center of the warp's pair
    int cc    = w * 2 + half_;
    int m     = m_base + cc;

    // ---- neighbor setup: lane (half_, k=l&15); one LDG.128 per gather ----
    {
        int k = l & 15;
        int n = idx[((size_t)b * M_ + m) * K_ + k];
        s_nidx[cc * 16 + k] = n;
        float4 pq = g_pos4[(size_t)b * N_ + n];
        const float* cp = cpos + ((size_t)b * M_ + m) * 3;
        s_npos[cc * 16 + k] = make_float4(pq.x - cp[0], pq.y - cp[1], pq.z - cp[2], 0.f);
    }
    __syncthreads();

    // ---- Phase A: logits + softmax (f32x2 logit loop, fp16 kgp 1-LDG row) ----
    {
        int k = l & 15;
        int n = s_nidx[cc * 16 + k];
        const float4* qwp = (const float4*)&g_qw[((size_t)b * M_ + m) * G_];
        float4 qa = qwp[0], qb = qwp[1];
        uint4 kg = *(const uint4*)&g_kgph[((size_t)b * N_ + n) * G_];
        float2 k01 = __half22float2(*reinterpret_cast<__half2*>(&kg.x));
        float2 k23 = __half22float2(*reinterpret_cast<__half2*>(&kg.y));
        float2 k45 = __half22float2(*reinterpret_cast<__half2*>(&kg.z));
        float2 k67 = __half22float2(*reinterpret_cast<__half2*>(&kg.w));
        float h[8];
        h[0] = fmaxf(k01.x + qa.x, 0.f); h[1] = fmaxf(k01.y + qa.y, 0.f);
        h[2] = fmaxf(k23.x + qa.z, 0.f); h[3] = fmaxf(k23.y + qa.w, 0.f);
        h[4] = fmaxf(k45.x + qb.x, 0.f); h[5] = fmaxf(k45.y + qb.y, 0.f);
        h[6] = fmaxf(k67.x + qb.z, 0.f); h[7] = fmaxf(k67.y + qb.w, 0.f);

        ull lgp[4];
        #pragma unroll
        for (int p = 0; p < 4; p++) lgp[p] = *(const ull*)&s_web2[2 * p];
        #pragma unroll
        for (int j = 0; j < 8; j++) {
            ull hp = pk2(h[j], h[j]);
            const ulonglong2* wr = (const ulonglong2*)&s_wew2[j * 8];
            ulonglong2 wa = wr[0], wb = wr[1];
            fma2(lgp[0], hp, wa.x); fma2(lgp[1], hp, wa.y);
            fma2(lgp[2], hp, wb.x); fma2(lgp[3], hp, wb.y);
        }
        float lg[8];
        #pragma unroll
        for (int p = 0; p < 4; p++) {
            float2 v = upk2(lgp[p]);
            lg[2 * p] = v.x; lg[2 * p + 1] = v.y;
        }
        float mx[8];
        #pragma unroll
        for (int u = 0; u < 8; u++) mx[u] = lg[u];
        #pragma unroll
        for (int mask = 1; mask <= 8; mask <<= 1)
            #pragma unroll
            for (int u = 0; u < 8; u++)
                mx[u] = fmaxf(mx[u], __shfl_xor_sync(0xffffffffu, mx[u], mask));
        float e[8], sm[8];
        #pragma unroll
        for (int u = 0; u < 8; u++) { e[u] = __expf(lg[u] - mx[u]); sm[u] = e[u]; }
        #pragma unroll
        for (int mask = 1; mask <= 8; mask <<= 1)
            #pragma unroll
            for (int u = 0; u < 8; u++)
                sm[u] += __shfl_xor_sync(0xffffffffu, sm[u], mask);
        float* wp = &s_wf[(cc * 16 + k) * 8];
        *(float4*)&wp[0] = make_float4(e[0] / sm[0], e[1] / sm[1], e[2] / sm[2], e[3] / sm[3]);
        *(float4*)&wp[4] = make_float4(e[4] / sm[4], e[5] / sm[5], e[6] / sm[6], e[7] / sm[7]);
    }
    __syncwarp();

    // ---- Phase B: S = T^T @ W via mma.sync m16n8k16; stage D to fp16 ----
    {
        int gp  = l >> 2;         // 0..7
        int ti  = l & 3;          // 0..3
        int kk0 = 2 * ti;

        #pragma unroll
        for (int c = 0; c < 2; c++) {
            int ccB = w * 2 + c;
            float4 npA = s_npos[ccB * 16 + kk0];
            float4 npB = s_npos[ccB * 16 + kk0 + 1];
            float4 npC = s_npos[ccB * 16 + kk0 + 8];
            float4 npD = s_npos[ccB * 16 + kk0 + 9];
            const float* wbv = &s_wf[ccB * 16 * 8];
            uint32_t b0 = h2u(wbv[kk0 * 8 + gp],       wbv[(kk0 + 1) * 8 + gp]);
            uint32_t b1 = h2u(wbv[(kk0 + 8) * 8 + gp], wbv[(kk0 + 9) * 8 + gp]);
            __half* dst = &s_stgh[ccB * (8 * 68)];

            #pragma unroll
            for (int tt = 0; tt < 4; tt++) {
                int j0 = 16 * tt + gp;
                float4 w0 = s_w1ps4[j0];
                float4 w1 = s_w1ps4[j0 + 8];
                float tA0 = fmaxf(fmaf(npA.z, w0.z, fmaf(npA.y, w0.y, fmaf(npA.x, w0.x, w0.w))), 0.f);
                float tB0 = fmaxf(fmaf(npB.z, w0.z, fmaf(npB.y, w0.y, fmaf(npB.x, w0.x, w0.w))), 0.f);
                float tC0 = fmaxf(fmaf(npC.z, w0.z, fmaf(npC.y, w0.y, fmaf(npC.x, w0.x, w0.w))), 0.f);
                float tD0 = fmaxf(fmaf(npD.z, w0.z, fmaf(npD.y, w0.y, fmaf(npD.x, w0.x, w0.w))), 0.f);
                float tA1 = fmaxf(fmaf(npA.z, w1.z, fmaf(npA.y, w1.y, fmaf(npA.x, w1.x, w1.w))), 0.f);
                float tB1 = fmaxf(fmaf(npB.z, w1.z, fmaf(npB.y, w1.y, fmaf(npB.x, w1.x, w1.w))), 0.f);
                float tC1 = fmaxf(fmaf(npC.z, w1.z, fmaf(npC.y, w1.y, fmaf(npC.x, w1.x, w1.w))), 0.f);
                float tD1 = fmaxf(fmaf(npD.z, w1.z, fmaf(npD.y, w1.y, fmaf(npD.x, w1.x, w1.w))), 0.f);

                uint32_t a0 = h2u(tA0, tB0);   // A[j0][kk0], A[j0][kk0+1]
                uint32_t a1 = h2u(tA1, tB1);   // A[j0+8][kk0..]
                uint32_t a2 = h2u(tC0, tD0);   // A[j0][kk0+8..]
                uint32_t a3 = h2u(tC1, tD1);   // A[j0+8][kk0+8..]

                float d0, d1, d2, d3;
                mma16816(d0, d1, d2, d3, a0, a1, a2, a3, b0, b1);
                // d0=S[j0][kk0], d1=S[j0][kk0+1], d2=S[j0+8][kk0], d3=S[j0+8][kk0+1]
                dst[(kk0)     * 68 + j0]     = __float2half_rn(d0);
                dst[(kk0 + 1) * 68 + j0]     = __float2half_rn(d1);
                dst[(kk0)     * 68 + j0 + 8] = __float2half_rn(d2);
                dst[(kk0 + 1) * 68 + j0 + 8] = __float2half_rn(d3);
            }
        }
    }
    __syncwarp();

    // ---- Phase C: R14 form (fp16 W2, scalar fma), S read from full rows ----
    {
        int lo = l & 15;
        int o0 = lo * 4;
        int g  = lo >> 1;
        float4 acc = *(const float4*)&s_peb2[o0];
        const __half* stg = &s_stgh[(w * 2 + half_) * (8 * 68) + g * 68];

        #pragma unroll
        for (int jb = 0; jb < 64; jb += 32) {
            #pragma unroll
            for (int jq = 0; jq < 32; jq += 4) {
                uint2 rs = *(const uint2*)&stg[jb + jq];
                float2 sa = __half22float2(*reinterpret_cast<__half2*>(&rs.x));
                float2 sb = __half22float2(*reinterpret_cast<__half2*>(&rs.y));
                const __half* wr = &s_pew2h[(jb + jq) * 68 + o0];
                float4 w20 = ld_h4(wr);
                float4 w21 = ld_h4(wr + 68);
                float4 w22 = ld_h4(wr + 136);
                float4 w23 = ld_h4(wr + 204);
                acc.x = fmaf(sa.x, w20.x, acc.x); acc.y = fmaf(sa.x, w20.y, acc.y);
                acc.z = fmaf(sa.x, w20.z, acc.z); acc.w = fmaf(sa.x, w20.w, acc.w);
                acc.x = fmaf(sa.y, w21.x, acc.x); acc.y = fmaf(sa.y, w21.y, acc.y);
                acc.z = fmaf(sa.y, w21.z, acc.z); acc.w = fmaf(sa.y, w21.w, acc.w);
                acc.x = fmaf(sb.x, w22.x, acc.x); acc.y = fmaf(sb.x, w22.y, acc.y);
                acc.z = fmaf(sb.x, w22.z, acc.z); acc.w = fmaf(sb.x, w22.w, acc.w);
                acc.x = fmaf(sb.y, w23.x, acc.x); acc.y = fmaf(sb.y, w23.y, acc.y);
                acc.z = fmaf(sb.y, w23.z, acc.z); acc.w = fmaf(sb.y, w23.w, acc.w);
            }
        }

        // xv gather part (fp16 rows, 128B per point)
        const __half* xvb = &g_xvh[((size_t)b * N_) * O_];
        #pragma unroll
        for (int kk = 0; kk < 16; kk++) {
            int   n  = s_nidx[cc * 16 + kk];
            float wk = s_wf[(cc * 16 + kk) * 8 + g];
            float4 xv = ld_h4(&xvb[(size_t)n * O_ + o0]);
            acc.x = fmaf(wk, xv.x, acc.x);
            acc.y = fmaf(wk, xv.y, acc.y);
            acc.z = fmaf(wk, xv.z, acc.z);
            acc.w = fmaf(wk, xv.w, acc.w);
        }
        *(float4*)&s_out[cc * 68 + o0] = acc;
    }
    __syncthreads();

    // ---- coalesced transposed store: out[b][o][m_base + 0..15] ----
    {
        int mm = t & 15;
        #pragma unroll
        for (int o = t >> 4; o < 64; o += 16)
            out[((size_t)b * O_ + o) * M_ + m_base + mm] = s_out[mm * 68 + o];
    }
}

// ============================================================================
extern "C" void kernel_launch(void* const* d_in, const int* in_sizes, int n_in,
                              void* d_out, int out_size)
{
    const float* center_pos = (const float*)d_in[0];
    const float* center_fea = (const float*)d_in[1];
    const float* pos        = (const float*)d_in[2];
    const float* fea        = (const float*)d_in[3];
    const int*   idx        = (const int*)  d_in[4];
    const float* Wq   = (const float*)d_in[5];
    const float* bq   = (const float*)d_in[6];
    const float* Wk   = (const float*)d_in[7];
    const float* bk   = (const float*)d_in[8];
    const float* Wv   = (const float*)d_in[9];
    const float* bv   = (const float*)d_in[10];
    const float* cpe_w1 = (const float*)d_in[11];
    const float* cpe_s  = (const float*)d_in[12];
    const float* cpe_b  = (const float*)d_in[13];
    const float* cpe_w2 = (const float*)d_in[14];
    const float* cpe_b2 = (const float*)d_in[15];
    const float* pe_w1  = (const float*)d_in[16];
    const float* pe_s   = (const float*)d_in[17];
    const float* pe_b   = (const float*)d_in[18];
    const float* pe_w2  = (const float*)d_in[19];
    const float* pe_b2  = (const float*)d_in[20];
    const float* we_w1  = (const float*)d_in[21];
    const float* we_s   = (const float*)d_in[22];
    const float* we_b   = (const float*)d_in[23];
    const float* we_w2  = (const float*)d_in[24];
    const float* we_b2  = (const float*)d_in[25];
    float* out = (float*)d_out;

    k0_fold<<<1, 512>>>(Wq, bq, Wk, bk, cpe_w2, cpe_b2, we_w1, we_s, we_b);

    dim3 g12(N_ / 64, B_, 2);
    k12<<<g12, 256>>>(fea, Wv, bv, pos, center_fea, center_pos,
                      cpe_w1, cpe_s, cpe_b);

    dim3 g3(M_ / 16, B_);
    k3_main<<<g3, 256>>>(center_pos, idx,
                         pe_w1, pe_s, pe_b, pe_w2, pe_b2,
                         we_w2, we_b2, out);
}